// round 15
// baseline (speedup 1.0000x reference)
#include <cuda_runtime.h>
#include <cuda_fp16.h>
#include <math.h>
#include <float.h>
#include <stdint.h>

// ---------------- problem constants ----------------
#define S_LEN   65536
#define H_DIM   512
#define A_DIM   256
#define H2_DIM  1024

#define BK         64
#define NIT        (H_DIM / BK)        // 8
#define NTHREADS   512

// heterogeneous tiling: 888 big (64-row) tiles = 3 full waves on 296 slots,
// then 272 small (32-row) tiles fill the tail wave at ~half length.
#define BIG_TILES   888
#define BIG_ROWS    (BIG_TILES * 64)   // 56832
#define SMALL_TILES 272                // * 32 = 8704 ; total = 65536
#define NUM_TILES   (BIG_TILES + SMALL_TILES)  // 1160

// f16 smem tiles: row pitch 72 halfwords (144 B), sized for the big path
#define SAH 72
#define A_H_BYTES (64 * SAH * 2)       // 9216
#define B_H_BYTES (256 * SAH * 2)      // 36864
#define BUF_H_BYTES (A_H_BYTES + B_H_BYTES)    // 46080 per buffer
#define EPI_OFF   (2 * BUF_H_BYTES)            // 92160
#define SMEM_BYTES (EPI_OFF + 1152 * 4)        // 96768 (x2 CTAs <= 228K)

#define CTX_BLOCKS 64
#define CTX_PER    19                  // ceil(1160/64); bounds-checked

// |e| <= sum|va| ~ 12.8 (|tanh|<=1) -> exp(e) fp32-safe, no max subtraction.

// ---------------- scratch ----------------
__device__ __half g_waH[A_DIM * H_DIM];
__device__ float g_encp[A_DIM];
__device__ float g_e[S_LEN];
__device__ float g_bl[NUM_TILES];
__device__ float g_part[NUM_TILES * H_DIM];
__device__ float g_p2[CTX_BLOCKS * H_DIM];
__device__ unsigned int g_done;

// ---------------- helpers ----------------
__device__ __forceinline__ float warp_sum(float v) {
    #pragma unroll
    for (int o = 16; o > 0; o >>= 1) v += __shfl_xor_sync(0xFFFFFFFFu, v, o);
    return v;
}
__device__ __forceinline__ uint32_t smem_u32(const void* p) {
    uint32_t a;
    asm("{ .reg .u64 t; cvta.to.shared.u64 t, %1; cvt.u32.u64 %0, t; }" : "=r"(a) : "l"(p));
    return a;
}
__device__ __forceinline__ void cp_async16(uint32_t dst, const void* src) {
    asm volatile("cp.async.cg.shared.global [%0], [%1], 16;" :: "r"(dst), "l"(src));
}
__device__ __forceinline__ uint32_t pack_h2(float lo, float hi) {
    uint32_t r;
    asm("cvt.rn.f16x2.f32 %0, %1, %2;" : "=r"(r) : "f"(hi), "f"(lo));
    return r;
}
__device__ __forceinline__ float tanh_fast(float x) {
    float y;
    asm("tanh.approx.f32 %0, %1;" : "=f"(y) : "f"(x));
    return y;
}
__device__ __forceinline__ void ldsm_x4(uint32_t& r0, uint32_t& r1, uint32_t& r2,
                                        uint32_t& r3, uint32_t addr) {
    asm volatile("ldmatrix.sync.aligned.m8n8.x4.shared.b16 {%0,%1,%2,%3}, [%4];"
                 : "=r"(r0), "=r"(r1), "=r"(r2), "=r"(r3) : "r"(addr));
}
__device__ __forceinline__ void mma_f16(float c[4], uint32_t a0, uint32_t a1,
                                        uint32_t a2, uint32_t a3,
                                        uint32_t b0, uint32_t b1) {
    asm volatile(
        "mma.sync.aligned.m16n8k16.row.col.f32.f16.f16.f32 "
        "{%0,%1,%2,%3}, {%4,%5,%6,%7}, {%8,%9}, {%0,%1,%2,%3};"
        : "+f"(c[0]), "+f"(c[1]), "+f"(c[2]), "+f"(c[3])
        : "r"(a0), "r"(a1), "r"(a2), "r"(a3), "r"(b0), "r"(b1));
}

// ---------------- kernel 1: prolog (Wa->f16 | enc_proj) -------------------
__global__ __launch_bounds__(512)
void k_prolog(const float* __restrict__ Wa, const float* __restrict__ enc,
              const float* __restrict__ Ua) {
    const int b = blockIdx.x;
    const int tid = threadIdx.x;
    if (b < 64) {
        int i = b * 512 + tid;
        float4 v = *(const float4*)(Wa + i * 4);
        uint32_t* dst = (uint32_t*)g_waH + i * 2;
        dst[0] = pack_h2(v.x, v.y);
        dst[1] = pack_h2(v.z, v.w);
    } else if (tid < 256) {
        int a = b - 64;
        float4 e4 = *(const float4*)(enc + tid * 4);
        float4 u4 = *(const float4*)(Ua + (size_t)a * H2_DIM + tid * 4);
        float s = e4.x * u4.x + e4.y * u4.y + e4.z * u4.z + e4.w * u4.w;
        __shared__ float red[8];
        s = warp_sum(s);
        int wid = tid >> 5, lane = tid & 31;
        if (lane == 0) red[wid] = s;
        __syncthreads();
        if (wid == 0) {
            float v = (lane < 8) ? red[lane] : 0.f;
            v = warp_sum(v);
            if (lane == 0) g_encp[a] = v;
        }
    }
}

// ---------------- scores tile body, templated on M-frags per warp ---------
// MW=2: 64-row tile (warp tile 32x32); MW=1: 32-row tile (warp tile 16x32).
template<int MW>
__device__ __forceinline__ void scores_tile(
    const float* __restrict__ si, const float* __restrict__ va,
    char* smem, int s0, int bidx)
{
    constexpr int ROWS = MW * 32;
    float* s_encp = (float*)(smem + EPI_OFF);           // 256
    float* s_va   = s_encp + 256;                       // 256
    float* s_red  = s_va + 256;                         // up to 64 x 9
    float* s_wt   = s_red + 576;                        // up to 64

    const int tid  = threadIdx.x;
    const int lane = tid & 31;
    const int wid  = tid >> 5;             // 0..15
    const int wm   = wid & 1;              // 2 warps in M
    const int wn   = wid >> 1;             // 8 warps in N (32 cols each)
    const int lt   = lane & 3;

    if (tid < 256) { s_encp[tid] = g_encp[tid]; s_va[tid] = va[tid]; }

    const uint32_t smem_base = smem_u32(smem);
    uint32_t addrA[MW], addrB[2];
    {
        int rowA = (lane & 15);
        int colA = (lane >> 4) * 8;
        #pragma unroll
        for (int m = 0; m < MW; m++)
            addrA[m] = smem_base +
                (uint32_t)((wm * (16 * MW) + m * 16 + rowA) * (SAH * 2) + colA * 2);
        int rowB = ((lane >> 4) << 3) + (lane & 7);
        int colB = ((lane >> 3) & 1) * 8;
        #pragma unroll
        for (int p = 0; p < 2; p++)
            addrB[p] = smem_base + A_H_BYTES +
                (uint32_t)((wn * 32 + p * 16 + rowB) * (SAH * 2) + colB * 2);
    }

    float acc[MW][4][4];
    #pragma unroll
    for (int m = 0; m < MW; m++)
        #pragma unroll
        for (int n = 0; n < 4; n++)
            #pragma unroll
            for (int j = 0; j < 4; j++) acc[m][n][j] = 0.f;

    float4 ra[MW];
    auto ldg_a = [&](int k0) {
        #pragma unroll
        for (int i = 0; i < MW; i++) {
            int ch = tid + i * NTHREADS;   // ROWS*16 chunks total
            ra[i] = *(const float4*)(si + (size_t)(s0 + (ch >> 4)) * H_DIM
                                     + k0 + (ch & 15) * 4);
        }
    };
    auto sts_a = [&](int buf) {
        uint32_t* hA = (uint32_t*)(smem + buf * BUF_H_BYTES);
        #pragma unroll
        for (int i = 0; i < MW; i++) {
            int ch = tid + i * NTHREADS;
            int base = (ch >> 4) * (SAH / 2) + (ch & 15) * 2;
            hA[base]     = pack_h2(ra[i].x, ra[i].y);
            hA[base + 1] = pack_h2(ra[i].z, ra[i].w);
        }
    };
    auto cpa_b = [&](int buf, int k0) {
        uint32_t bB = smem_base + (uint32_t)(buf * BUF_H_BYTES + A_H_BYTES);
        #pragma unroll
        for (int i = 0; i < 4; i++) {
            int ch = tid + i * NTHREADS;
            int r = ch >> 3, c4 = ch & 7;
            cp_async16(bB + r * (SAH * 2) + c4 * 16,
                       g_waH + (size_t)r * H_DIM + k0 + c4 * 8);
        }
        asm volatile("cp.async.commit_group;" ::: "memory");
    };

    ldg_a(0);
    sts_a(0);
    cpa_b(0, 0);
    ldg_a(BK);
    asm volatile("cp.async.wait_group 0;" ::: "memory");
    __syncthreads();

    for (int c = 0; c < NIT; c++) {
        if (c + 1 < NIT) {
            sts_a((c + 1) & 1);
            cpa_b((c + 1) & 1, (c + 1) * BK);
        }
        if (c + 2 < NIT) ldg_a((c + 2) * BK);

        const uint32_t boff = (uint32_t)((c & 1) * BUF_H_BYTES);
        #pragma unroll
        for (int ks = 0; ks < 4; ks++) {
            const uint32_t koff = boff + ks * 32;
            uint32_t af[MW][4], bf[2][4];
            #pragma unroll
            for (int m = 0; m < MW; m++)
                ldsm_x4(af[m][0], af[m][1], af[m][2], af[m][3], addrA[m] + koff);
            #pragma unroll
            for (int p = 0; p < 2; p++)
                ldsm_x4(bf[p][0], bf[p][1], bf[p][2], bf[p][3], addrB[p] + koff);
            #pragma unroll
            for (int m = 0; m < MW; m++) {
                mma_f16(acc[m][0], af[m][0], af[m][1], af[m][2], af[m][3],
                        bf[0][0], bf[0][1]);
                mma_f16(acc[m][1], af[m][0], af[m][1], af[m][2], af[m][3],
                        bf[0][2], bf[0][3]);
                mma_f16(acc[m][2], af[m][0], af[m][1], af[m][2], af[m][3],
                        bf[1][0], bf[1][1]);
                mma_f16(acc[m][3], af[m][0], af[m][1], af[m][2], af[m][3],
                        bf[1][2], bf[1][3]);
            }
        }
        if (c + 1 < NIT)
            asm volatile("cp.async.wait_group 0;" ::: "memory");
        __syncthreads();
    }

    // -------- epilogue: e = sum_a tanh(acc + encp)·va, per row --------
    float rowsum[MW][2];
    #pragma unroll
    for (int m = 0; m < MW; m++) { rowsum[m][0] = 0.f; rowsum[m][1] = 0.f; }

    #pragma unroll
    for (int n = 0; n < 4; n++) {
        int cb = wn * 32 + n * 8 + lt * 2;
        float e0 = s_encp[cb],     v0 = s_va[cb];
        float e1 = s_encp[cb + 1], v1 = s_va[cb + 1];
        #pragma unroll
        for (int m = 0; m < MW; m++) {
            rowsum[m][0] += tanh_fast(acc[m][n][0] + e0) * v0
                          + tanh_fast(acc[m][n][1] + e1) * v1;
            rowsum[m][1] += tanh_fast(acc[m][n][2] + e0) * v0
                          + tanh_fast(acc[m][n][3] + e1) * v1;
        }
    }
    #pragma unroll
    for (int m = 0; m < MW; m++)
        #pragma unroll
        for (int h = 0; h < 2; h++) {
            rowsum[m][h] += __shfl_xor_sync(0xFFFFFFFFu, rowsum[m][h], 1);
            rowsum[m][h] += __shfl_xor_sync(0xFFFFFFFFu, rowsum[m][h], 2);
        }
    if (lt == 0) {
        int lg = lane >> 2;
        #pragma unroll
        for (int m = 0; m < MW; m++)
            #pragma unroll
            for (int h = 0; h < 2; h++) {
                int row = wm * (16 * MW) + m * 16 + lg + h * 8;
                s_red[row * 9 + wn] = rowsum[m][h];
            }
    }
    __syncthreads();

    // no-max softmax: w = exp(e) directly
    float w_val = 0.f;
    if (tid < ROWS) {
        float s = 0.f;
        #pragma unroll
        for (int j = 0; j < 8; j++) s += s_red[tid * 9 + j];
        g_e[s0 + tid] = s;
        w_val = expf(s);
        s_wt[tid] = w_val;
    }

    __shared__ float s_p[2];
    float lw = warp_sum(w_val);
    if (tid < ROWS && lane == 0) s_p[wid] = lw;
    __syncthreads();
    if (tid == 0) {
        float L = s_p[0];
        if (MW == 2) L += s_p[1];
        g_bl[bidx] = L;
    }

    // fused unnormalized context partials (si tile L2-hot)
    {
        float cacc = 0.f;
        const float* base = si + (size_t)s0 * H_DIM + tid;
        #pragma unroll 4
        for (int r = 0; r < ROWS; r++)
            cacc = fmaf(s_wt[r], base[(size_t)r * H_DIM], cacc);
        g_part[(size_t)bidx * H_DIM + tid] = cacc;
    }
}

// ---------------- kernel 2: heterogeneous score GEMM ----------------------
__global__ __launch_bounds__(NTHREADS, 2)
void k_scores_mma(const float* __restrict__ si, const float* __restrict__ va) {
    extern __shared__ __align__(16) char smem[];
    const int b = blockIdx.x;
    if (b < BIG_TILES) {
        scores_tile<2>(si, va, smem, b * 64, b);
    } else {
        int j = b - BIG_TILES;
        scores_tile<1>(si, va, smem, BIG_ROWS + j * 32, b);
    }
}

// ---------------- kernel 3: ctx partials + alpha + last-block finish ------
__global__ __launch_bounds__(512)
void k_ctx(float* __restrict__ out) {
    __shared__ float red[16];
    __shared__ float sL;
    __shared__ unsigned int slast;
    const int chunk = blockIdx.x;         // 64 blocks
    const int tid = threadIdx.x;          // 512
    const int wid = tid >> 5, lane = tid & 31;

    // ---- L = sum of per-tile exp-sums over 1160 tiles ----
    float l = g_bl[tid] + g_bl[tid + 512];
    if (tid < NUM_TILES - 1024) l += g_bl[tid + 1024];
    float wl = warp_sum(l);
    if (lane == 0) red[wid] = wl;
    __syncthreads();
    if (tid == 0) {
        float L = 0.f;
        #pragma unroll
        for (int i = 0; i < 16; i++) L += red[i];
        sL = L;
    }
    __syncthreads();
    const float inv_l = 1.f / sL;

    // ---- stage-1 context partials: up to 19 tiles per block ----
    float s = 0.f;
    int b0 = chunk * CTX_PER;
    int b1 = min(b0 + CTX_PER, NUM_TILES);
    for (int b = b0; b < b1; b++)
        s += g_part[(size_t)b * H_DIM + tid];
    g_p2[chunk * H_DIM + tid] = s;

    // ---- alpha for this chunk's 1024 scores ----
    {
        int i = chunk * 1024 + tid * 2;
        float2 e = *(const float2*)(g_e + i);
        float2 r;
        r.x = expf(e.x) * inv_l;
        r.y = expf(e.y) * inv_l;
        *(float2*)(out + H_DIM + i) = r;
    }

    // ---- last block finishes the context reduction ----
    __threadfence();
    if (tid == 0) slast = atomicAdd(&g_done, 1u);
    __syncthreads();
    if (slast == CTX_BLOCKS - 1) {
        float t = 0.f;
        #pragma unroll 8
        for (int c = 0; c < CTX_BLOCKS; c++)
            t += g_p2[c * H_DIM + tid];
        out[tid] = t * inv_l;
        if (tid == 0) g_done = 0;
    }
}

// ---------------- launch ---------------------------------------------------
extern "C" void kernel_launch(void* const* d_in, const int* in_sizes, int n_in,
                              void* d_out, int out_size) {
    const float* enc = (const float*)d_in[0];
    const float* si  = (const float*)d_in[1];
    const float* Wa  = (const float*)d_in[2];
    const float* Ua  = (const float*)d_in[3];
    const float* va  = (const float*)d_in[4];
    float* out = (float*)d_out;

    cudaFuncSetAttribute(k_scores_mma,
                         cudaFuncAttributeMaxDynamicSharedMemorySize, SMEM_BYTES);

    k_prolog<<<320, 512>>>(Wa, enc, Ua);
    k_scores_mma<<<NUM_TILES, NTHREADS, SMEM_BYTES>>>(si, va);
    k_ctx<<<CTX_BLOCKS, 512>>>(out);
}

// round 16
// speedup vs baseline: 1.0698x; 1.0698x over previous
#include <cuda_runtime.h>
#include <cuda_fp16.h>
#include <math.h>
#include <float.h>
#include <stdint.h>

// ---------------- problem constants ----------------
#define S_LEN   65536
#define H_DIM   512
#define A_DIM   256
#define H2_DIM  1024

#define TILE_M     64
#define NUM_TILES  (S_LEN / TILE_M)    // 1024
#define BK         64
#define NIT        (H_DIM / BK)        // 8
#define NTHREADS   512                 // 16 warps: wm(2) x wn(8), warp tile 32x32

// f16 smem tiles: row pitch 72 halfwords (144 B) for BK=64
#define SAH 72
#define A_H_BYTES (64 * SAH * 2)       // 9216
#define B_H_BYTES (256 * SAH * 2)      // 36864
#define BUF_H_BYTES (A_H_BYTES + B_H_BYTES)    // 46080 per buffer
#define EPI_OFF   (2 * BUF_H_BYTES)            // 92160
#define SMEM_BYTES (EPI_OFF + 1152 * 4)        // 96768 (x2 CTAs <= 228K)

#define CTX_BLOCKS 64
#define CTX_PER    (NUM_TILES / CTX_BLOCKS)    // 16

// |e| <= sum|va| ~ 12.8 (|tanh|<=1) -> exp(e) fp32-safe, no max subtraction.
// g_e stores w = exp(e); alpha = w * inv_L.

// ---------------- scratch ----------------
__device__ __half g_waH[A_DIM * H_DIM];        // Wa pre-converted to f16
__device__ float g_encp[A_DIM];
__device__ float g_e[S_LEN];                   // holds exp(e)
__device__ float g_bl[NUM_TILES];              // per-tile sum of exp(e)
__device__ float g_part[NUM_TILES * H_DIM];    // unnormalized context partials
__device__ float g_p2[CTX_BLOCKS * H_DIM];
__device__ unsigned int g_done;                // zero-init; self-resetting

// ---------------- helpers ----------------
__device__ __forceinline__ float warp_sum(float v) {
    #pragma unroll
    for (int o = 16; o > 0; o >>= 1) v += __shfl_xor_sync(0xFFFFFFFFu, v, o);
    return v;
}
__device__ __forceinline__ uint32_t smem_u32(const void* p) {
    uint32_t a;
    asm("{ .reg .u64 t; cvta.to.shared.u64 t, %1; cvt.u32.u64 %0, t; }" : "=r"(a) : "l"(p));
    return a;
}
__device__ __forceinline__ void cp_async16(uint32_t dst, const void* src) {
    asm volatile("cp.async.cg.shared.global [%0], [%1], 16;" :: "r"(dst), "l"(src));
}
__device__ __forceinline__ uint32_t pack_h2(float lo, float hi) {
    uint32_t r;
    asm("cvt.rn.f16x2.f32 %0, %1, %2;" : "=r"(r) : "f"(hi), "f"(lo));
    return r;
}
__device__ __forceinline__ float tanh_fast(float x) {
    float y;
    asm("tanh.approx.f32 %0, %1;" : "=f"(y) : "f"(x));
    return y;
}
__device__ __forceinline__ void ldsm_x4(uint32_t& r0, uint32_t& r1, uint32_t& r2,
                                        uint32_t& r3, uint32_t addr) {
    asm volatile("ldmatrix.sync.aligned.m8n8.x4.shared.b16 {%0,%1,%2,%3}, [%4];"
                 : "=r"(r0), "=r"(r1), "=r"(r2), "=r"(r3) : "r"(addr));
}
__device__ __forceinline__ void mma_f16(float c[4], uint32_t a0, uint32_t a1,
                                        uint32_t a2, uint32_t a3,
                                        uint32_t b0, uint32_t b1) {
    asm volatile(
        "mma.sync.aligned.m16n8k16.row.col.f32.f16.f16.f32 "
        "{%0,%1,%2,%3}, {%4,%5,%6,%7}, {%8,%9}, {%0,%1,%2,%3};"
        : "+f"(c[0]), "+f"(c[1]), "+f"(c[2]), "+f"(c[3])
        : "r"(a0), "r"(a1), "r"(a2), "r"(a3), "r"(b0), "r"(b1));
}

// ---------------- kernel 1: prolog (Wa->f16 | enc_proj) -------------------
__global__ __launch_bounds__(512)
void k_prolog(const float* __restrict__ Wa, const float* __restrict__ enc,
              const float* __restrict__ Ua) {
    const int b = blockIdx.x;
    const int tid = threadIdx.x;
    if (b < 64) {
        int i = b * 512 + tid;                     // float4 index (32768 total)
        float4 v = *(const float4*)(Wa + i * 4);
        uint32_t* dst = (uint32_t*)g_waH + i * 2;
        dst[0] = pack_h2(v.x, v.y);
        dst[1] = pack_h2(v.z, v.w);
    } else if (tid < 256) {
        int a = b - 64;
        float4 e4 = *(const float4*)(enc + tid * 4);
        float4 u4 = *(const float4*)(Ua + (size_t)a * H2_DIM + tid * 4);
        float s = e4.x * u4.x + e4.y * u4.y + e4.z * u4.z + e4.w * u4.w;
        __shared__ float red[8];
        s = warp_sum(s);
        int wid = tid >> 5, lane = tid & 31;
        if (lane == 0) red[wid] = s;
        __syncthreads();
        if (wid == 0) {
            float v = (lane < 8) ? red[lane] : 0.f;
            v = warp_sum(v);
            if (lane == 0) g_encp[a] = v;
        }
    }
}

// ---------------- kernel 2: f16 score GEMM, TILE_M=64, BK=64, occ 2 -------
__global__ __launch_bounds__(NTHREADS, 2)
void k_scores_mma(const float* __restrict__ si, const float* __restrict__ va) {
    extern __shared__ __align__(16) char smem[];
    float* s_encp = (float*)(smem + EPI_OFF);           // 256
    float* s_va   = s_encp + 256;                       // 256
    float* s_red  = s_va + 256;                         // 64 x 9
    float* s_wt   = s_red + 576;                        // 64

    const int tid  = threadIdx.x;
    const int lane = tid & 31;
    const int wid  = tid >> 5;             // 0..15
    const int wm   = wid & 1;              // 2 warps in M (32 rows each)
    const int wn   = wid >> 1;             // 8 warps in N (32 cols each)
    const int s0   = blockIdx.x * TILE_M;
    const int lt   = lane & 3;             // 0..3

    if (tid < 256) { s_encp[tid] = g_encp[tid]; s_va[tid] = va[tid]; }

    const uint32_t smem_base = smem_u32(smem);
    uint32_t addrA[2], addrB[2];
    {
        int rowA = (lane & 15);
        int colA = (lane >> 4) * 8;
        #pragma unroll
        for (int m = 0; m < 2; m++)
            addrA[m] = smem_base +
                (uint32_t)((wm * 32 + m * 16 + rowA) * (SAH * 2) + colA * 2);
        int rowB = ((lane >> 4) << 3) + (lane & 7);
        int colB = ((lane >> 3) & 1) * 8;
        #pragma unroll
        for (int p = 0; p < 2; p++)
            addrB[p] = smem_base + A_H_BYTES +
                (uint32_t)((wn * 32 + p * 16 + rowB) * (SAH * 2) + colB * 2);
    }

    float acc[2][4][4];
    #pragma unroll
    for (int m = 0; m < 2; m++)
        #pragma unroll
        for (int n = 0; n < 4; n++)
            #pragma unroll
            for (int j = 0; j < 4; j++) acc[m][n][j] = 0.f;

    float4 ra[2];
    auto ldg_a2 = [&](int k0) {
        int ch0 = tid, ch1 = tid + NTHREADS;
        ra[0] = *(const float4*)(si + (size_t)(s0 + (ch0 >> 4)) * H_DIM + k0 + (ch0 & 15) * 4);
        ra[1] = *(const float4*)(si + (size_t)(s0 + (ch1 >> 4)) * H_DIM + k0 + (ch1 & 15) * 4);
    };
    auto sts_a = [&](int buf) {
        uint32_t* hA = (uint32_t*)(smem + buf * BUF_H_BYTES);
        #pragma unroll
        for (int i = 0; i < 2; i++) {
            int ch = tid + i * NTHREADS;
            int r = ch >> 4, c4 = ch & 15;
            int base = r * (SAH / 2) + c4 * 2;
            hA[base]     = pack_h2(ra[i].x, ra[i].y);
            hA[base + 1] = pack_h2(ra[i].z, ra[i].w);
        }
    };
    auto cpa_b = [&](int buf, int k0) {
        uint32_t bB = smem_base + (uint32_t)(buf * BUF_H_BYTES + A_H_BYTES);
        #pragma unroll
        for (int i = 0; i < 4; i++) {
            int ch = tid + i * NTHREADS;
            int r = ch >> 3, c4 = ch & 7;
            cp_async16(bB + r * (SAH * 2) + c4 * 16,
                       g_waH + (size_t)r * H_DIM + k0 + c4 * 8);
        }
        asm volatile("cp.async.commit_group;" ::: "memory");
    };

    ldg_a2(0);
    sts_a(0);
    cpa_b(0, 0);
    ldg_a2(BK);
    asm volatile("cp.async.wait_group 0;" ::: "memory");
    __syncthreads();

    for (int c = 0; c < NIT; c++) {
        if (c + 1 < NIT) {
            sts_a((c + 1) & 1);
            cpa_b((c + 1) & 1, (c + 1) * BK);
        }
        if (c + 2 < NIT) ldg_a2((c + 2) * BK);

        const uint32_t boff = (uint32_t)((c & 1) * BUF_H_BYTES);
        #pragma unroll
        for (int ks = 0; ks < 4; ks++) {       // four K=16 steps per BK=64
            const uint32_t koff = boff + ks * 32;
            uint32_t af[2][4], bf[2][4];
            #pragma unroll
            for (int m = 0; m < 2; m++)
                ldsm_x4(af[m][0], af[m][1], af[m][2], af[m][3], addrA[m] + koff);
            #pragma unroll
            for (int p = 0; p < 2; p++)
                ldsm_x4(bf[p][0], bf[p][1], bf[p][2], bf[p][3], addrB[p] + koff);
            #pragma unroll
            for (int m = 0; m < 2; m++) {
                mma_f16(acc[m][0], af[m][0], af[m][1], af[m][2], af[m][3],
                        bf[0][0], bf[0][1]);
                mma_f16(acc[m][1], af[m][0], af[m][1], af[m][2], af[m][3],
                        bf[0][2], bf[0][3]);
                mma_f16(acc[m][2], af[m][0], af[m][1], af[m][2], af[m][3],
                        bf[1][0], bf[1][1]);
                mma_f16(acc[m][3], af[m][0], af[m][1], af[m][2], af[m][3],
                        bf[1][2], bf[1][3]);
            }
        }
        if (c + 1 < NIT)
            asm volatile("cp.async.wait_group 0;" ::: "memory");
        __syncthreads();
    }

    // -------- epilogue: e = sum_a tanh(acc + encp)·va, per row --------
    float rowsum[2][2];
    #pragma unroll
    for (int m = 0; m < 2; m++) { rowsum[m][0] = 0.f; rowsum[m][1] = 0.f; }

    #pragma unroll
    for (int n = 0; n < 4; n++) {
        int cb = wn * 32 + n * 8 + lt * 2;
        float e0 = s_encp[cb],     v0 = s_va[cb];
        float e1 = s_encp[cb + 1], v1 = s_va[cb + 1];
        #pragma unroll
        for (int m = 0; m < 2; m++) {
            rowsum[m][0] += tanh_fast(acc[m][n][0] + e0) * v0
                          + tanh_fast(acc[m][n][1] + e1) * v1;
            rowsum[m][1] += tanh_fast(acc[m][n][2] + e0) * v0
                          + tanh_fast(acc[m][n][3] + e1) * v1;
        }
    }
    #pragma unroll
    for (int m = 0; m < 2; m++)
        #pragma unroll
        for (int h = 0; h < 2; h++) {
            rowsum[m][h] += __shfl_xor_sync(0xFFFFFFFFu, rowsum[m][h], 1);
            rowsum[m][h] += __shfl_xor_sync(0xFFFFFFFFu, rowsum[m][h], 2);
        }
    if (lt == 0) {
        int lg = lane >> 2;
        #pragma unroll
        for (int m = 0; m < 2; m++)
            #pragma unroll
            for (int h = 0; h < 2; h++) {
                int row = wm * 32 + m * 16 + lg + h * 8;
                s_red[row * 9 + wn] = rowsum[m][h];
            }
    }
    __syncthreads();

    // no-max softmax: w = exp(e) directly (|e| <= ~13, fp32-safe).
    // g_e stores w so k_ctx never recomputes exp.
    float w_val = 0.f;
    if (tid < 64) {
        float s = 0.f;
        #pragma unroll
        for (int j = 0; j < 8; j++) s += s_red[tid * 9 + j];
        w_val = expf(s);
        g_e[s0 + tid] = w_val;
        s_wt[tid] = w_val;
    }

    __shared__ float s_p[2];
    float lw = warp_sum(w_val);
    if (tid < 64 && lane == 0) s_p[wid] = lw;
    __syncthreads();
    if (tid == 0) g_bl[blockIdx.x] = s_p[0] + s_p[1];

    // fused unnormalized context partials (si tile L2-hot)
    {
        float cacc = 0.f;
        const float* base = si + (size_t)s0 * H_DIM + tid;
        #pragma unroll 4
        for (int r = 0; r < TILE_M; r++)
            cacc = fmaf(s_wt[r], base[(size_t)r * H_DIM], cacc);
        g_part[(size_t)blockIdx.x * H_DIM + tid] = cacc;
    }
}

// ---------------- kernel 3: ctx partials + alpha + last-block finish ------
__global__ __launch_bounds__(512)
void k_ctx(float* __restrict__ out) {
    __shared__ float red[16];
    __shared__ float sL;
    __shared__ unsigned int slast;
    const int chunk = blockIdx.x;         // 64 blocks
    const int tid = threadIdx.x;          // 512
    const int wid = tid >> 5, lane = tid & 31;

    // ---- L = sum of per-tile exp-sums (single pass, no max) ----
    float l = g_bl[tid] + g_bl[tid + 512];
    float wl = warp_sum(l);
    if (lane == 0) red[wid] = wl;
    __syncthreads();
    if (tid == 0) {
        float L = 0.f;
        #pragma unroll
        for (int i = 0; i < 16; i++) L += red[i];
        sL = L;
    }
    __syncthreads();
    const float inv_l = 1.f / sL;

    // ---- stage-1 context partials for this chunk ----
    float s = 0.f;
    #pragma unroll
    for (int b = chunk * CTX_PER; b < (chunk + 1) * CTX_PER; b++)
        s += g_part[(size_t)b * H_DIM + tid];
    g_p2[chunk * H_DIM + tid] = s;

    // ---- alpha for this chunk's 1024 scores (g_e holds exp(e)) ----
    {
        int i = chunk * 1024 + tid * 2;
        float2 w = *(const float2*)(g_e + i);
        float2 r;
        r.x = w.x * inv_l;
        r.y = w.y * inv_l;
        *(float2*)(out + H_DIM + i) = r;
    }

    // ---- last block finishes the context reduction ----
    __threadfence();
    if (tid == 0) slast = atomicAdd(&g_done, 1u);
    __syncthreads();
    if (slast == CTX_BLOCKS - 1) {
        float t = 0.f;
        #pragma unroll 8
        for (int c = 0; c < CTX_BLOCKS; c++)
            t += g_p2[c * H_DIM + tid];
        out[tid] = t * inv_l;
        if (tid == 0) g_done = 0;          // reset for next graph replay
    }
}

// ---------------- launch ---------------------------------------------------
extern "C" void kernel_launch(void* const* d_in, const int* in_sizes, int n_in,
                              void* d_out, int out_size) {
    const float* enc = (const float*)d_in[0];
    const float* si  = (const float*)d_in[1];
    const float* Wa  = (const float*)d_in[2];
    const float* Ua  = (const float*)d_in[3];
    const float* va  = (const float*)d_in[4];
    float* out = (float*)d_out;

    cudaFuncSetAttribute(k_scores_mma,
                         cudaFuncAttributeMaxDynamicSharedMemorySize, SMEM_BYTES);

    k_prolog<<<320, 512>>>(Wa, enc, Ua);
    k_scores_mma<<<NUM_TILES, NTHREADS, SMEM_BYTES>>>(si, va);
    k_ctx<<<CTX_BLOCKS, 512>>>(out);
}